// round 3
// baseline (speedup 1.0000x reference)
#include <cuda_runtime.h>
#include <math.h>

#define Nn   50000
#define Ee   800000
#define HIDc 128
#define MLPc 512
#define MODSc 768

// ---------------- scratch (device globals; no allocation allowed) ----------
__device__ float g_sc  [Nn * HIDc];     // silu(c)
__device__ float g_mods[Nn * MODSc];    // adaLN modulation params
__device__ float g_xmod[Nn * HIDc];     // modulated ln(x) (reused for both LN sites)
__device__ float g_qkv [Nn * 3 * HIDc];
__device__ float g_score[(size_t)Ee * 8];
__device__ float g_smax[Nn * 8];
__device__ float g_den [Nn * 8];
__device__ float g_agg [Nn * HIDc];
__device__ float g_x1  [Nn * HIDc];     // x after attn residual
__device__ float g_h1  [Nn * MLPc];     // mlp hidden
__device__ int   g_src [Ee];
__device__ int   g_dst [Ee];
__device__ int   g_is64;

// ---------------- helpers ---------------------------------------------------
__device__ __forceinline__ void atomicMaxFloat(float* addr, float value) {
    if (value >= 0.0f)
        atomicMax((int*)addr, __float_as_int(value));
    else
        atomicMin((unsigned int*)addr, __float_as_uint(value));
}

__device__ __forceinline__ void redAdd4(float* addr, float4 v) {
    asm volatile("red.global.add.v4.f32 [%0], {%1, %2, %3, %4};"
                 :: "l"(addr), "f"(v.x), "f"(v.y), "f"(v.z), "f"(v.w)
                 : "memory");
}

// ---------------- edge-index dtype probe + conversion ------------------------
__global__ void k_flag_init() { g_is64 = 1; }

// Reading the first Ee elements as int64 is in-bounds whether the buffer holds
// 2*Ee int32 (== Ee*8 bytes) or 2*Ee int64. If any value interpreted as int64
// falls outside [0, Nn), the buffer must be int32.
__global__ void k_detect(const void* __restrict__ ei) {
    int t = blockIdx.x * blockDim.x + threadIdx.x;
    if (t >= Ee) return;
    long long v = ((const long long*)ei)[t];
    if (v < 0 || v >= (long long)Nn) g_is64 = 0;
}

__global__ void k_convert(const void* __restrict__ ei) {
    int t = blockIdx.x * blockDim.x + threadIdx.x;
    if (t >= Ee) return;
    if (g_is64) {
        g_src[t] = (int)((const long long*)ei)[t];
        g_dst[t] = (int)((const long long*)ei)[Ee + t];
    } else {
        g_src[t] = ((const int*)ei)[t];
        g_dst[t] = ((const int*)ei)[Ee + t];
    }
}

// ---------------- elementwise kernels ---------------------------------------
__global__ void k_silu(const float* __restrict__ c, float* __restrict__ out) {
    int t = blockIdx.x * blockDim.x + threadIdx.x;
    if (t >= Nn * HIDc) return;
    float v = c[t];
    out[t] = v / (1.0f + expf(-v));
}

__global__ void k_init() {
    int t = blockIdx.x * blockDim.x + threadIdx.x;
    if (t < Nn * HIDc) g_agg[t] = 0.0f;
    if (t < Nn * 8) { g_den[t] = 0.0f; g_smax[t] = -INFINITY; }
}

// LayerNorm + modulate: out = ln(x)*(1+scale)+shift ; one warp per row
__global__ void k_ln_mod(const float* __restrict__ x, const float* __restrict__ mods,
                         int shift_off, int scale_off, float* __restrict__ out) {
    int warp = (blockIdx.x * blockDim.x + threadIdx.x) >> 5;
    int lane = threadIdx.x & 31;
    if (warp >= Nn) return;
    const float4 xv = *(const float4*)&x[(size_t)warp * HIDc + lane * 4];
    float s  = xv.x + xv.y + xv.z + xv.w;
    float s2 = xv.x*xv.x + xv.y*xv.y + xv.z*xv.z + xv.w*xv.w;
    #pragma unroll
    for (int o = 16; o; o >>= 1) {
        s  += __shfl_xor_sync(0xffffffffu, s,  o);
        s2 += __shfl_xor_sync(0xffffffffu, s2, o);
    }
    float mean = s * (1.0f / 128.0f);
    float var  = s2 * (1.0f / 128.0f) - mean * mean;
    float rstd = rsqrtf(var + 1e-6f);
    const float4 sh = *(const float4*)&mods[(size_t)warp * MODSc + shift_off + lane * 4];
    const float4 sc = *(const float4*)&mods[(size_t)warp * MODSc + scale_off + lane * 4];
    float4 o4;
    o4.x = (xv.x - mean) * rstd * (1.0f + sc.x) + sh.x;
    o4.y = (xv.y - mean) * rstd * (1.0f + sc.y) + sh.y;
    o4.z = (xv.z - mean) * rstd * (1.0f + sc.z) + sh.z;
    o4.w = (xv.w - mean) * rstd * (1.0f + sc.w) + sh.w;
    *(float4*)&out[(size_t)warp * HIDc + lane * 4] = o4;
}

// ---------------- edge kernels ----------------------------------------------
__global__ void k_edge_score(const float* __restrict__ qkv) {
    long long t = (long long)blockIdx.x * blockDim.x + threadIdx.x;
    if (t >= (long long)Ee * 8) return;
    int e = (int)(t >> 3);
    int h = (int)(t & 7);
    int src = g_src[e];
    int dst = g_dst[e];
    const float* q = &qkv[(size_t)dst * 384 + h * 16];
    const float* k = &qkv[(size_t)src * 384 + 128 + h * 16];
    float d = 0.0f;
    #pragma unroll
    for (int i = 0; i < 4; i++) {
        float4 qv = *(const float4*)&q[i * 4];
        float4 kv = *(const float4*)&k[i * 4];
        d += qv.x*kv.x + qv.y*kv.y + qv.z*kv.z + qv.w*kv.w;
    }
    d *= 0.25f;  // 1/sqrt(16)
    g_score[t] = d;
    atomicMaxFloat(&g_smax[dst * 8 + h], d);
}

__global__ void k_edge_msg(const float* __restrict__ qkv) {
    long long t = (long long)blockIdx.x * blockDim.x + threadIdx.x;
    if (t >= (long long)Ee * 8) return;
    int e = (int)(t >> 3);
    int h = (int)(t & 7);
    int src = g_src[e];
    int dst = g_dst[e];
    float sc = g_score[t];
    float ex = expf(sc - g_smax[dst * 8 + h]);
    atomicAdd(&g_den[dst * 8 + h], ex);
    const float* v = &qkv[(size_t)src * 384 + 256 + h * 16];
    float* a = &g_agg[(size_t)dst * HIDc + h * 16];
    #pragma unroll
    for (int i = 0; i < 4; i++) {
        float4 vv = *(const float4*)&v[i * 4];
        redAdd4(&a[i * 4], make_float4(vv.x * ex, vv.y * ex, vv.z * ex, vv.w * ex));
    }
}

__global__ void k_norm() {
    int t = blockIdx.x * blockDim.x + threadIdx.x;   // over Nn*32 float4s
    if (t >= Nn * 32) return;
    int n = t >> 5;
    int h = (t >> 2) & 7;
    float dd = g_den[n * 8 + h];
    float inv = (dd > 0.0f) ? (1.0f / dd) : 0.0f;
    float4 v = *(float4*)&g_agg[t * 4];
    v.x *= inv; v.y *= inv; v.z *= inv; v.w *= inv;
    *(float4*)&g_agg[t * 4] = v;
}

// ---------------- SGEMM: 128x128 tile, BK=16, 256 threads, 8x8 microtile ----
// C[M,Ncol] = epi(A[M,K] @ B[K,Ncol] + bias)
// EPI 0: plain (+bias)   EPI 1: gelu(tanh)   EPI 2: resid + gate*(acc+bias)
template<int EPI>
__global__ __launch_bounds__(256)
void sgemm128(const float* __restrict__ A, const float* __restrict__ B,
              const float* __restrict__ bias, float* __restrict__ C,
              int M, int Ncol, int K,
              const float* __restrict__ resid,
              const float* __restrict__ gate, int gate_stride) {
    __shared__ float As[16][132];   // [k][row], padded
    __shared__ float Bs[16][128];   // [k][col]
    int tid = threadIdx.x;
    int tx = tid & 15, ty = tid >> 4;
    int rowBase = blockIdx.y * 128;
    int colBase = blockIdx.x * 128;

    float acc[8][8];
    #pragma unroll
    for (int i = 0; i < 8; i++)
        #pragma unroll
        for (int j = 0; j < 8; j++) acc[i][j] = 0.0f;

    for (int k0 = 0; k0 < K; k0 += 16) {
        // A tile: 128 rows x 16 k, transposed into As[k][row]
        #pragma unroll
        for (int li = 0; li < 2; li++) {
            int id = tid + li * 256;        // 0..511
            int r  = id >> 2;               // 0..127
            int kc = (id & 3) * 4;
            int grow = rowBase + r;
            float4 v = make_float4(0.f, 0.f, 0.f, 0.f);
            if (grow < M) v = *(const float4*)&A[(size_t)grow * K + k0 + kc];
            As[kc + 0][r] = v.x; As[kc + 1][r] = v.y;
            As[kc + 2][r] = v.z; As[kc + 3][r] = v.w;
        }
        // B tile: 16 k x 128 cols
        #pragma unroll
        for (int li = 0; li < 2; li++) {
            int id = tid + li * 256;
            int kr = id >> 5;               // 0..15
            int c  = (id & 31) * 4;
            *(float4*)&Bs[kr][c] = *(const float4*)&B[(size_t)(k0 + kr) * Ncol + colBase + c];
        }
        __syncthreads();
        #pragma unroll
        for (int kk = 0; kk < 16; kk++) {
            float a[8], b[8];
            *(float4*)&a[0] = *(float4*)&As[kk][ty * 8];
            *(float4*)&a[4] = *(float4*)&As[kk][ty * 8 + 4];
            *(float4*)&b[0] = *(float4*)&Bs[kk][tx * 8];
            *(float4*)&b[4] = *(float4*)&Bs[kk][tx * 8 + 4];
            #pragma unroll
            for (int i = 0; i < 8; i++)
                #pragma unroll
                for (int j = 0; j < 8; j++)
                    acc[i][j] = fmaf(a[i], b[j], acc[i][j]);
        }
        __syncthreads();
    }

    #pragma unroll
    for (int i = 0; i < 8; i++) {
        int grow = rowBase + ty * 8 + i;
        if (grow >= M) continue;
        #pragma unroll
        for (int j = 0; j < 8; j++) {
            int col = colBase + tx * 8 + j;
            float v = acc[i][j] + (bias ? bias[col] : 0.0f);
            if (EPI == 1) {
                float t = 0.7978845608028654f * (v + 0.044715f * v * v * v);
                v = 0.5f * v * (1.0f + tanhf(t));
            } else if (EPI == 2) {
                float g = gate[(size_t)grow * gate_stride + col];
                v = resid[(size_t)grow * Ncol + col] + g * v;
            }
            C[(size_t)grow * Ncol + col] = v;
        }
    }
}

// ---------------- launch ----------------------------------------------------
extern "C" void kernel_launch(void* const* d_in, const int* in_sizes, int n_in,
                              void* d_out, int out_size) {
    const float* x      = (const float*)d_in[0];
    const void*  ei     = d_in[1];                // int32 or int64 — probed on device
    const float* c      = (const float*)d_in[2];
    const float* w_qkv  = (const float*)d_in[3];
    const float* w_proj = (const float*)d_in[4];
    const float* b_proj = (const float*)d_in[5];
    const float* w_mlp1 = (const float*)d_in[6];
    const float* b_mlp1 = (const float*)d_in[7];
    const float* w_mlp2 = (const float*)d_in[8];
    const float* b_mlp2 = (const float*)d_in[9];
    const float* w_ada  = (const float*)d_in[10];
    const float* b_ada  = (const float*)d_in[11];
    float* out = (float*)d_out;

    float *p_sc, *p_mods, *p_xmod, *p_qkv, *p_agg, *p_x1, *p_h1;
    cudaGetSymbolAddress((void**)&p_sc,   g_sc);
    cudaGetSymbolAddress((void**)&p_mods, g_mods);
    cudaGetSymbolAddress((void**)&p_xmod, g_xmod);
    cudaGetSymbolAddress((void**)&p_qkv,  g_qkv);
    cudaGetSymbolAddress((void**)&p_agg,  g_agg);
    cudaGetSymbolAddress((void**)&p_x1,   g_x1);
    cudaGetSymbolAddress((void**)&p_h1,   g_h1);

    const int rowsB = (Nn + 127) / 128;   // 391

    // 0) edge-index dtype probe + conversion to int32 src/dst
    k_flag_init<<<1, 1>>>();
    k_detect <<<(Ee + 255) / 256, 256>>>(ei);
    k_convert<<<(Ee + 255) / 256, 256>>>(ei);

    // 1) silu(c)
    k_silu<<<(Nn * HIDc + 255) / 256, 256>>>(c, p_sc);
    // 2) mods = silu(c) @ w_ada + b_ada
    sgemm128<0><<<dim3(MODSc / 128, rowsB), 256>>>(p_sc, w_ada, b_ada, p_mods,
                                                   Nn, MODSc, HIDc, nullptr, nullptr, 0);
    // 3) xmod = modulate(ln(x), sh_msa, sc_msa)
    k_ln_mod<<<(Nn + 7) / 8, 256>>>(x, p_mods, 0, HIDc, p_xmod);
    // 4) qkv = xmod @ w_qkv
    sgemm128<0><<<dim3(384 / 128, rowsB), 256>>>(p_xmod, w_qkv, nullptr, p_qkv,
                                                 Nn, 384, HIDc, nullptr, nullptr, 0);
    // 5) init attn scratch
    k_init<<<(Nn * HIDc + 255) / 256, 256>>>();
    // 6) per-edge scores + segment max
    k_edge_score<<<(Ee * 8) / 256, 256>>>(p_qkv);
    // 7) per-edge exp + denominator + weighted message accumulation
    k_edge_msg<<<(Ee * 8) / 256, 256>>>(p_qkv);
    // 8) normalize aggregation by denominator
    k_norm<<<(Nn * 32 + 255) / 256, 256>>>();
    // 9) x1 = x + g_msa * (agg @ w_proj + b_proj)
    sgemm128<2><<<dim3(1, rowsB), 256>>>(p_agg, w_proj, b_proj, p_x1,
                                         Nn, HIDc, HIDc, x, p_mods + 2 * HIDc, MODSc);
    // 10) xmod = modulate(ln(x1), sh_mlp, sc_mlp)
    k_ln_mod<<<(Nn + 7) / 8, 256>>>(p_x1, p_mods, 3 * HIDc, 4 * HIDc, p_xmod);
    // 11) h1 = gelu(xmod @ w_mlp1 + b_mlp1)
    sgemm128<1><<<dim3(MLPc / 128, rowsB), 256>>>(p_xmod, w_mlp1, b_mlp1, p_h1,
                                                  Nn, MLPc, HIDc, nullptr, nullptr, 0);
    // 12) out = x1 + g_mlp * (h1 @ w_mlp2 + b_mlp2)
    sgemm128<2><<<dim3(1, rowsB), 256>>>(p_h1, w_mlp2, b_mlp2, out,
                                         Nn, HIDc, MLPc, p_x1, p_mods + 5 * HIDc, MODSc);
}

// round 4
// speedup vs baseline: 1.2005x; 1.2005x over previous
#include <cuda_runtime.h>
#include <math.h>

#define Nn   50000
#define Ee   800000
#define HIDc 128
#define MLPc 512
#define MODSc 768

// ---------------- scratch (device globals; no allocation allowed) ----------
__device__ float g_sc  [Nn * HIDc];
__device__ float g_mods[Nn * MODSc];
__device__ float g_xmod[Nn * HIDc];
__device__ float g_qkv [Nn * 3 * HIDc];
__device__ float g_score[(size_t)Ee * 8];
__device__ float g_smax[Nn * 8];
__device__ float g_den [Nn * 8];
__device__ float g_agg [Nn * HIDc];
__device__ float g_x1  [Nn * HIDc];
__device__ float g_h1  [Nn * MLPc];
__device__ int   g_src [Ee];
__device__ int   g_dst [Ee];
__device__ int   g_is64;

// ---------------- helpers ---------------------------------------------------
__device__ __forceinline__ void atomicMaxFloat(float* addr, float value) {
    if (value >= 0.0f)
        atomicMax((int*)addr, __float_as_int(value));
    else
        atomicMin((unsigned int*)addr, __float_as_uint(value));
}

__device__ __forceinline__ void redAdd4(float* addr, float4 v) {
    asm volatile("red.global.add.v4.f32 [%0], {%1, %2, %3, %4};"
                 :: "l"(addr), "f"(v.x), "f"(v.y), "f"(v.z), "f"(v.w)
                 : "memory");
}

__device__ __forceinline__ unsigned tf32_of(float f) {
    unsigned r;
    asm("cvt.rna.tf32.f32 %0, %1;" : "=r"(r) : "f"(f));
    return r;
}

__device__ __forceinline__ void mma8(float* c, const unsigned* a, const unsigned* b) {
    asm volatile("mma.sync.aligned.m16n8k8.row.col.f32.tf32.tf32.f32 "
                 "{%0,%1,%2,%3}, {%4,%5,%6,%7}, {%8,%9}, {%0,%1,%2,%3};"
                 : "+f"(c[0]), "+f"(c[1]), "+f"(c[2]), "+f"(c[3])
                 : "r"(a[0]), "r"(a[1]), "r"(a[2]), "r"(a[3]),
                   "r"(b[0]), "r"(b[1]));
}

// ---------------- edge-index dtype probe + conversion ------------------------
__global__ void k_flag_init() { g_is64 = 1; }

__global__ void k_detect(const void* __restrict__ ei) {
    int t = blockIdx.x * blockDim.x + threadIdx.x;
    if (t >= Ee) return;
    long long v = ((const long long*)ei)[t];
    if (v < 0 || v >= (long long)Nn) g_is64 = 0;
}

__global__ void k_convert(const void* __restrict__ ei) {
    int t = blockIdx.x * blockDim.x + threadIdx.x;
    if (t >= Ee) return;
    if (g_is64) {
        g_src[t] = (int)((const long long*)ei)[t];
        g_dst[t] = (int)((const long long*)ei)[Ee + t];
    } else {
        g_src[t] = ((const int*)ei)[t];
        g_dst[t] = ((const int*)ei)[Ee + t];
    }
}

// ---------------- elementwise kernels ---------------------------------------
__global__ void k_silu(const float* __restrict__ c, float* __restrict__ out) {
    int t = blockIdx.x * blockDim.x + threadIdx.x;
    if (t >= Nn * HIDc) return;
    float v = c[t];
    out[t] = v / (1.0f + expf(-v));
}

__global__ void k_init() {
    int t = blockIdx.x * blockDim.x + threadIdx.x;
    if (t < Nn * HIDc) g_agg[t] = 0.0f;
    if (t < Nn * 8) { g_den[t] = 0.0f; g_smax[t] = -INFINITY; }
}

__global__ void k_ln_mod(const float* __restrict__ x, const float* __restrict__ mods,
                         int shift_off, int scale_off, float* __restrict__ out) {
    int warp = (blockIdx.x * blockDim.x + threadIdx.x) >> 5;
    int lane = threadIdx.x & 31;
    if (warp >= Nn) return;
    const float4 xv = *(const float4*)&x[(size_t)warp * HIDc + lane * 4];
    float s  = xv.x + xv.y + xv.z + xv.w;
    float s2 = xv.x*xv.x + xv.y*xv.y + xv.z*xv.z + xv.w*xv.w;
    #pragma unroll
    for (int o = 16; o; o >>= 1) {
        s  += __shfl_xor_sync(0xffffffffu, s,  o);
        s2 += __shfl_xor_sync(0xffffffffu, s2, o);
    }
    float mean = s * (1.0f / 128.0f);
    float var  = s2 * (1.0f / 128.0f) - mean * mean;
    float rstd = rsqrtf(var + 1e-6f);
    const float4 sh = *(const float4*)&mods[(size_t)warp * MODSc + shift_off + lane * 4];
    const float4 sc = *(const float4*)&mods[(size_t)warp * MODSc + scale_off + lane * 4];
    float4 o4;
    o4.x = (xv.x - mean) * rstd * (1.0f + sc.x) + sh.x;
    o4.y = (xv.y - mean) * rstd * (1.0f + sc.y) + sh.y;
    o4.z = (xv.z - mean) * rstd * (1.0f + sc.z) + sh.z;
    o4.w = (xv.w - mean) * rstd * (1.0f + sc.w) + sh.w;
    *(float4*)&out[(size_t)warp * HIDc + lane * 4] = o4;
}

// ---------------- edge kernels ----------------------------------------------
__global__ void k_edge_score(const float* __restrict__ qkv) {
    long long t = (long long)blockIdx.x * blockDim.x + threadIdx.x;
    if (t >= (long long)Ee * 8) return;
    int e = (int)(t >> 3);
    int h = (int)(t & 7);
    int src = g_src[e];
    int dst = g_dst[e];
    const float* q = &qkv[(size_t)dst * 384 + h * 16];
    const float* k = &qkv[(size_t)src * 384 + 128 + h * 16];
    float d = 0.0f;
    #pragma unroll
    for (int i = 0; i < 4; i++) {
        float4 qv = *(const float4*)&q[i * 4];
        float4 kv = *(const float4*)&k[i * 4];
        d += qv.x*kv.x + qv.y*kv.y + qv.z*kv.z + qv.w*kv.w;
    }
    d *= 0.25f;
    g_score[t] = d;
    atomicMaxFloat(&g_smax[dst * 8 + h], d);
}

__global__ void k_edge_msg(const float* __restrict__ qkv) {
    long long t = (long long)blockIdx.x * blockDim.x + threadIdx.x;
    if (t >= (long long)Ee * 8) return;
    int e = (int)(t >> 3);
    int h = (int)(t & 7);
    int src = g_src[e];
    int dst = g_dst[e];
    float sc = g_score[t];
    float ex = expf(sc - g_smax[dst * 8 + h]);
    atomicAdd(&g_den[dst * 8 + h], ex);
    const float* v = &qkv[(size_t)src * 384 + 256 + h * 16];
    float* a = &g_agg[(size_t)dst * HIDc + h * 16];
    #pragma unroll
    for (int i = 0; i < 4; i++) {
        float4 vv = *(const float4*)&v[i * 4];
        redAdd4(&a[i * 4], make_float4(vv.x * ex, vv.y * ex, vv.z * ex, vv.w * ex));
    }
}

__global__ void k_norm() {
    int t = blockIdx.x * blockDim.x + threadIdx.x;
    if (t >= Nn * 32) return;
    int n = t >> 5;
    int h = (t >> 2) & 7;
    float dd = g_den[n * 8 + h];
    float inv = (dd > 0.0f) ? (1.0f / dd) : 0.0f;
    float4 v = *(float4*)&g_agg[t * 4];
    v.x *= inv; v.y *= inv; v.z *= inv; v.w *= inv;
    *(float4*)&g_agg[t * 4] = v;
}

// ---------------- 3xTF32 tensor-core GEMM -----------------------------------
// C[M,N] = epi(A[M,K] @ B[K,N] + bias)
// 128x128 block tile, BK=16, 256 threads (8 warps, 2x4 warp grid, 64x32 warp tile)
// EPI 0: +bias   EPI 1: gelu(tanh)   EPI 2: resid + gate*(acc+bias)
#define BKg 16
#define PADM 136

template<int EPI>
__global__ __launch_bounds__(256)
void tgemm128(const float* __restrict__ A, const float* __restrict__ B,
              const float* __restrict__ bias, float* __restrict__ C,
              int M, int N, int K,
              const float* __restrict__ resid,
              const float* __restrict__ gate, int gate_stride) {
    __shared__ unsigned Ahi[BKg][PADM], Alo[BKg][PADM];
    __shared__ unsigned Bhi[BKg][PADM], Blo[BKg][PADM];

    const int tid = threadIdx.x;
    const int warpId = tid >> 5;
    const int lane = tid & 31;
    const int gr = lane >> 2;          // 0..7
    const int tg = lane & 3;           // 0..3
    const int warpRow = warpId >> 2;   // 0..1  -> m offset *64
    const int warpCol = warpId & 3;    // 0..3  -> n offset *32
    const int rowBase = blockIdx.y * 128;
    const int colBase = blockIdx.x * 128;

    float acc[4][4][4];
    #pragma unroll
    for (int i = 0; i < 4; i++)
        #pragma unroll
        for (int j = 0; j < 4; j++)
            #pragma unroll
            for (int r = 0; r < 4; r++) acc[i][j][r] = 0.0f;

    for (int k0 = 0; k0 < K; k0 += BKg) {
        // A tile: 128 rows x 16 k -> split hi/lo, transposed [k][m]
        #pragma unroll
        for (int li = 0; li < 2; li++) {
            int id = tid + li * 256;          // 0..511 float4 slots
            int r  = id >> 2;                 // 0..127
            int kc = (id & 3) * 4;
            int grow = rowBase + r;
            float4 v = make_float4(0.f, 0.f, 0.f, 0.f);
            if (grow < M) v = *(const float4*)&A[(size_t)grow * K + k0 + kc];
            float vv[4] = {v.x, v.y, v.z, v.w};
            #pragma unroll
            for (int j = 0; j < 4; j++) {
                unsigned h = tf32_of(vv[j]);
                Ahi[kc + j][r] = h;
                Alo[kc + j][r] = tf32_of(vv[j] - __uint_as_float(h));
            }
        }
        // B tile: 16 k x 128 n -> split hi/lo, [k][n]
        #pragma unroll
        for (int li = 0; li < 2; li++) {
            int id = tid + li * 256;
            int kr = id >> 5;                 // 0..15
            int cc = (id & 31) * 4;
            float4 v = *(const float4*)&B[(size_t)(k0 + kr) * N + colBase + cc];
            float vv[4] = {v.x, v.y, v.z, v.w};
            #pragma unroll
            for (int j = 0; j < 4; j++) {
                unsigned h = tf32_of(vv[j]);
                Bhi[kr][cc + j] = h;
                Blo[kr][cc + j] = tf32_of(vv[j] - __uint_as_float(h));
            }
        }
        __syncthreads();

        #pragma unroll
        for (int kk = 0; kk < BKg; kk += 8) {
            unsigned ah[4][4], al[4][4], bh[4][2], bl[4][2];
            #pragma unroll
            for (int mi = 0; mi < 4; mi++) {
                int m0 = warpRow * 64 + mi * 16;
                ah[mi][0] = Ahi[kk + tg    ][m0 + gr];
                ah[mi][1] = Ahi[kk + tg    ][m0 + gr + 8];
                ah[mi][2] = Ahi[kk + tg + 4][m0 + gr];
                ah[mi][3] = Ahi[kk + tg + 4][m0 + gr + 8];
                al[mi][0] = Alo[kk + tg    ][m0 + gr];
                al[mi][1] = Alo[kk + tg    ][m0 + gr + 8];
                al[mi][2] = Alo[kk + tg + 4][m0 + gr];
                al[mi][3] = Alo[kk + tg + 4][m0 + gr + 8];
            }
            #pragma unroll
            for (int ni = 0; ni < 4; ni++) {
                int n0 = warpCol * 32 + ni * 8;
                bh[ni][0] = Bhi[kk + tg    ][n0 + gr];
                bh[ni][1] = Bhi[kk + tg + 4][n0 + gr];
                bl[ni][0] = Blo[kk + tg    ][n0 + gr];
                bl[ni][1] = Blo[kk + tg + 4][n0 + gr];
            }
            #pragma unroll
            for (int mi = 0; mi < 4; mi++)
                #pragma unroll
                for (int ni = 0; ni < 4; ni++) {
                    mma8(acc[mi][ni], ah[mi], bh[ni]);
                    mma8(acc[mi][ni], ah[mi], bl[ni]);
                    mma8(acc[mi][ni], al[mi], bh[ni]);
                }
        }
        __syncthreads();
    }

    // epilogue
    #pragma unroll
    for (int mi = 0; mi < 4; mi++) {
        #pragma unroll
        for (int half = 0; half < 2; half++) {
            int row = rowBase + warpRow * 64 + mi * 16 + gr + half * 8;
            if (row >= M) continue;
            #pragma unroll
            for (int ni = 0; ni < 4; ni++) {
                int col = colBase + warpCol * 32 + ni * 8 + tg * 2;
                float v0 = acc[mi][ni][half * 2 + 0] + (bias ? bias[col]     : 0.0f);
                float v1 = acc[mi][ni][half * 2 + 1] + (bias ? bias[col + 1] : 0.0f);
                if (EPI == 1) {
                    float t0 = 0.7978845608028654f * (v0 + 0.044715f * v0 * v0 * v0);
                    v0 = 0.5f * v0 * (1.0f + tanhf(t0));
                    float t1 = 0.7978845608028654f * (v1 + 0.044715f * v1 * v1 * v1);
                    v1 = 0.5f * v1 * (1.0f + tanhf(t1));
                } else if (EPI == 2) {
                    float g0 = gate[(size_t)row * gate_stride + col];
                    float g1 = gate[(size_t)row * gate_stride + col + 1];
                    v0 = resid[(size_t)row * N + col]     + g0 * v0;
                    v1 = resid[(size_t)row * N + col + 1] + g1 * v1;
                }
                *(float2*)&C[(size_t)row * N + col] = make_float2(v0, v1);
            }
        }
    }
}

// ---------------- launch ----------------------------------------------------
extern "C" void kernel_launch(void* const* d_in, const int* in_sizes, int n_in,
                              void* d_out, int out_size) {
    const float* x      = (const float*)d_in[0];
    const void*  ei     = d_in[1];
    const float* c      = (const float*)d_in[2];
    const float* w_qkv  = (const float*)d_in[3];
    const float* w_proj = (const float*)d_in[4];
    const float* b_proj = (const float*)d_in[5];
    const float* w_mlp1 = (const float*)d_in[6];
    const float* b_mlp1 = (const float*)d_in[7];
    const float* w_mlp2 = (const float*)d_in[8];
    const float* b_mlp2 = (const float*)d_in[9];
    const float* w_ada  = (const float*)d_in[10];
    const float* b_ada  = (const float*)d_in[11];
    float* out = (float*)d_out;

    float *p_sc, *p_mods, *p_xmod, *p_qkv, *p_agg, *p_x1, *p_h1;
    cudaGetSymbolAddress((void**)&p_sc,   g_sc);
    cudaGetSymbolAddress((void**)&p_mods, g_mods);
    cudaGetSymbolAddress((void**)&p_xmod, g_xmod);
    cudaGetSymbolAddress((void**)&p_qkv,  g_qkv);
    cudaGetSymbolAddress((void**)&p_agg,  g_agg);
    cudaGetSymbolAddress((void**)&p_x1,   g_x1);
    cudaGetSymbolAddress((void**)&p_h1,   g_h1);

    const int rowsB = (Nn + 127) / 128;   // 391

    // 0) edge-index dtype probe + conversion
    k_flag_init<<<1, 1>>>();
    k_detect <<<(Ee + 255) / 256, 256>>>(ei);
    k_convert<<<(Ee + 255) / 256, 256>>>(ei);

    // 1) silu(c)
    k_silu<<<(Nn * HIDc + 255) / 256, 256>>>(c, p_sc);
    // 2) mods = silu(c) @ w_ada + b_ada
    tgemm128<0><<<dim3(MODSc / 128, rowsB), 256>>>(p_sc, w_ada, b_ada, p_mods,
                                                   Nn, MODSc, HIDc, nullptr, nullptr, 0);
    // 3) xmod = modulate(ln(x), sh_msa, sc_msa)
    k_ln_mod<<<(Nn + 7) / 8, 256>>>(x, p_mods, 0, HIDc, p_xmod);
    // 4) qkv = xmod @ w_qkv
    tgemm128<0><<<dim3(384 / 128, rowsB), 256>>>(p_xmod, w_qkv, nullptr, p_qkv,
                                                 Nn, 384, HIDc, nullptr, nullptr, 0);
    // 5) init attn scratch
    k_init<<<(Nn * HIDc + 255) / 256, 256>>>();
    // 6) per-edge scores + segment max
    k_edge_score<<<(Ee * 8) / 256, 256>>>(p_qkv);
    // 7) per-edge exp + denominator + message accumulation
    k_edge_msg<<<(Ee * 8) / 256, 256>>>(p_qkv);
    // 8) normalize
    k_norm<<<(Nn * 32 + 255) / 256, 256>>>();
    // 9) x1 = x + g_msa * (agg @ w_proj + b_proj)
    tgemm128<2><<<dim3(1, rowsB), 256>>>(p_agg, w_proj, b_proj, p_x1,
                                         Nn, HIDc, HIDc, x, p_mods + 2 * HIDc, MODSc);
    // 10) xmod = modulate(ln(x1), sh_mlp, sc_mlp)
    k_ln_mod<<<(Nn + 7) / 8, 256>>>(p_x1, p_mods, 3 * HIDc, 4 * HIDc, p_xmod);
    // 11) h1 = gelu(xmod @ w_mlp1 + b_mlp1)
    tgemm128<1><<<dim3(MLPc / 128, rowsB), 256>>>(p_xmod, w_mlp1, b_mlp1, p_h1,
                                                  Nn, MLPc, HIDc, nullptr, nullptr, 0);
    // 12) out = x1 + g_mlp * (h1 @ w_mlp2 + b_mlp2)
    tgemm128<2><<<dim3(1, rowsB), 256>>>(p_h1, w_mlp2, b_mlp2, out,
                                         Nn, HIDc, MLPc, p_x1, p_mods + 5 * HIDc, MODSc);
}

// round 5
// speedup vs baseline: 1.4515x; 1.2091x over previous
#include <cuda_runtime.h>
#include <cuda_bf16.h>
#include <math.h>

#define Nn   50000
#define Ee   800000
#define HIDc 128
#define MLPc 512
#define MODSc 768

// ---------------- scratch (device globals; no allocation allowed) ----------
__device__ float g_sc  [Nn * HIDc];
__device__ float g_mods[Nn * MODSc];
__device__ float g_xmod[Nn * HIDc];
__device__ float g_qkv [Nn * 3 * HIDc];
__device__ float g_score[(size_t)Ee * 8];
__device__ float g_smax[Nn * 8];
__device__ float g_den [Nn * 8];
__device__ float g_agg [Nn * HIDc];
__device__ float g_x1  [Nn * HIDc];
__device__ float g_h1  [Nn * MLPc];
__device__ int   g_src [Ee];
__device__ int   g_dst [Ee];
__device__ int   g_is64;

// ---------------- helpers ---------------------------------------------------
__device__ __forceinline__ void atomicMaxFloat(float* addr, float value) {
    if (value >= 0.0f)
        atomicMax((int*)addr, __float_as_int(value));
    else
        atomicMin((unsigned int*)addr, __float_as_uint(value));
}

__device__ __forceinline__ void redAdd4(float* addr, float4 v) {
    asm volatile("red.global.add.v4.f32 [%0], {%1, %2, %3, %4};"
                 :: "l"(addr), "f"(v.x), "f"(v.y), "f"(v.z), "f"(v.w)
                 : "memory");
}

// split a float pair into packed bf16x2 hi and lo
__device__ __forceinline__ void bf16_split2(float e, float o, unsigned& hi, unsigned& lo) {
    __nv_bfloat162 h2 = __floats2bfloat162_rn(e, o);
    float he = __bfloat162float(h2.x);
    float ho = __bfloat162float(h2.y);
    __nv_bfloat162 l2 = __floats2bfloat162_rn(e - he, o - ho);
    hi = *(unsigned*)&h2;
    lo = *(unsigned*)&l2;
}

__device__ __forceinline__ void mma16(float* c, const unsigned* a, const unsigned* b) {
    asm volatile("mma.sync.aligned.m16n8k16.row.col.f32.bf16.bf16.f32 "
                 "{%0,%1,%2,%3}, {%4,%5,%6,%7}, {%8,%9}, {%0,%1,%2,%3};"
                 : "+f"(c[0]), "+f"(c[1]), "+f"(c[2]), "+f"(c[3])
                 : "r"(a[0]), "r"(a[1]), "r"(a[2]), "r"(a[3]),
                   "r"(b[0]), "r"(b[1]));
}

// ---------------- edge-index dtype probe + conversion ------------------------
__global__ void k_flag_init() { g_is64 = 1; }

__global__ void k_detect(const void* __restrict__ ei) {
    int t = blockIdx.x * blockDim.x + threadIdx.x;
    if (t >= Ee) return;
    long long v = ((const long long*)ei)[t];
    if (v < 0 || v >= (long long)Nn) g_is64 = 0;
}

__global__ void k_convert(const void* __restrict__ ei) {
    int t = blockIdx.x * blockDim.x + threadIdx.x;
    if (t >= Ee) return;
    if (g_is64) {
        g_src[t] = (int)((const long long*)ei)[t];
        g_dst[t] = (int)((const long long*)ei)[Ee + t];
    } else {
        g_src[t] = ((const int*)ei)[t];
        g_dst[t] = ((const int*)ei)[Ee + t];
    }
}

// ---------------- elementwise kernels ---------------------------------------
__global__ void k_silu(const float* __restrict__ c, float* __restrict__ out) {
    int t = blockIdx.x * blockDim.x + threadIdx.x;
    if (t >= Nn * HIDc) return;
    float v = c[t];
    out[t] = v / (1.0f + expf(-v));
}

__global__ void k_init() {
    int t = blockIdx.x * blockDim.x + threadIdx.x;
    if (t < Nn * HIDc) g_agg[t] = 0.0f;
    if (t < Nn * 8) { g_den[t] = 0.0f; g_smax[t] = -INFINITY; }
}

__global__ void k_ln_mod(const float* __restrict__ x, const float* __restrict__ mods,
                         int shift_off, int scale_off, float* __restrict__ out) {
    int warp = (blockIdx.x * blockDim.x + threadIdx.x) >> 5;
    int lane = threadIdx.x & 31;
    if (warp >= Nn) return;
    const float4 xv = *(const float4*)&x[(size_t)warp * HIDc + lane * 4];
    float s  = xv.x + xv.y + xv.z + xv.w;
    float s2 = xv.x*xv.x + xv.y*xv.y + xv.z*xv.z + xv.w*xv.w;
    #pragma unroll
    for (int o = 16; o; o >>= 1) {
        s  += __shfl_xor_sync(0xffffffffu, s,  o);
        s2 += __shfl_xor_sync(0xffffffffu, s2, o);
    }
    float mean = s * (1.0f / 128.0f);
    float var  = s2 * (1.0f / 128.0f) - mean * mean;
    float rstd = rsqrtf(var + 1e-6f);
    const float4 sh = *(const float4*)&mods[(size_t)warp * MODSc + shift_off + lane * 4];
    const float4 sc = *(const float4*)&mods[(size_t)warp * MODSc + scale_off + lane * 4];
    float4 o4;
    o4.x = (xv.x - mean) * rstd * (1.0f + sc.x) + sh.x;
    o4.y = (xv.y - mean) * rstd * (1.0f + sc.y) + sh.y;
    o4.z = (xv.z - mean) * rstd * (1.0f + sc.z) + sh.z;
    o4.w = (xv.w - mean) * rstd * (1.0f + sc.w) + sh.w;
    *(float4*)&out[(size_t)warp * HIDc + lane * 4] = o4;
}

// ---------------- edge kernels ----------------------------------------------
__global__ void k_edge_score(const float* __restrict__ qkv) {
    long long t = (long long)blockIdx.x * blockDim.x + threadIdx.x;
    if (t >= (long long)Ee * 8) return;
    int e = (int)(t >> 3);
    int h = (int)(t & 7);
    int src = g_src[e];
    int dst = g_dst[e];
    const float* q = &qkv[(size_t)dst * 384 + h * 16];
    const float* k = &qkv[(size_t)src * 384 + 128 + h * 16];
    float d = 0.0f;
    #pragma unroll
    for (int i = 0; i < 4; i++) {
        float4 qv = *(const float4*)&q[i * 4];
        float4 kv = *(const float4*)&k[i * 4];
        d += qv.x*kv.x + qv.y*kv.y + qv.z*kv.z + qv.w*kv.w;
    }
    d *= 0.25f;
    g_score[t] = d;
    atomicMaxFloat(&g_smax[dst * 8 + h], d);
}

__global__ void k_edge_msg(const float* __restrict__ qkv) {
    long long t = (long long)blockIdx.x * blockDim.x + threadIdx.x;
    if (t >= (long long)Ee * 8) return;
    int e = (int)(t >> 3);
    int h = (int)(t & 7);
    int src = g_src[e];
    int dst = g_dst[e];
    float sc = g_score[t];
    float ex = expf(sc - g_smax[dst * 8 + h]);
    atomicAdd(&g_den[dst * 8 + h], ex);
    const float* v = &qkv[(size_t)src * 384 + 256 + h * 16];
    float* a = &g_agg[(size_t)dst * HIDc + h * 16];
    #pragma unroll
    for (int i = 0; i < 4; i++) {
        float4 vv = *(const float4*)&v[i * 4];
        redAdd4(&a[i * 4], make_float4(vv.x * ex, vv.y * ex, vv.z * ex, vv.w * ex));
    }
}

__global__ void k_norm() {
    int t = blockIdx.x * blockDim.x + threadIdx.x;
    if (t >= Nn * 32) return;
    int n = t >> 5;
    int h = (t >> 2) & 7;
    float dd = g_den[n * 8 + h];
    float inv = (dd > 0.0f) ? (1.0f / dd) : 0.0f;
    float4 v = *(float4*)&g_agg[t * 4];
    v.x *= inv; v.y *= inv; v.z *= inv; v.w *= inv;
    *(float4*)&g_agg[t * 4] = v;
}

// ---------------- 3xBF16 tensor-core GEMM -----------------------------------
// C[M,N] = epi(A[M,K] @ B[K,N] + bias)
// 128x128 block tile, BK=16 (8 packed bf16x2 k-pairs), 256 threads,
// 8 warps (2x4 warp grid, 64x32 warp tile), mma.m16n8k16.bf16.
// A = Ahi+Alo, B = Bhi+Blo; compute hi*hi + hi*lo + lo*hi (fp32 accum).
// EPI 0: +bias   EPI 1: gelu(tanh)   EPI 2: resid + gate*(acc+bias)
#define PADg 136

template<int EPI>
__global__ __launch_bounds__(256)
void bgemm128(const float* __restrict__ A, const float* __restrict__ B,
              const float* __restrict__ bias, float* __restrict__ C,
              int M, int N, int K,
              const float* __restrict__ resid,
              const float* __restrict__ gate, int gate_stride) {
    __shared__ unsigned Ahip[8][PADg], Alop[8][PADg];
    __shared__ unsigned Bhip[8][PADg], Blop[8][PADg];

    const int tid = threadIdx.x;
    const int warpId = tid >> 5;
    const int lane = tid & 31;
    const int gr = lane >> 2;          // 0..7
    const int tg = lane & 3;           // 0..3
    const int warpRow = warpId >> 2;   // 0..1  (m offset *64)
    const int warpCol = warpId & 3;    // 0..3  (n offset *32)
    const int rowBase = blockIdx.y * 128;
    const int colBase = blockIdx.x * 128;

    // A fill mapping: r = tid&127 (row), half = tid>>7 (k half: 8 floats)
    const int ar = tid & 127;
    const int ahalf = tid >> 7;
    // B fill mapping: kp = tid>>5 (packed k row), n0 = (tid&31)*4
    const int bkp = tid >> 5;
    const int bn0 = (lane) * 4;

    float acc[4][4][4];
    #pragma unroll
    for (int i = 0; i < 4; i++)
        #pragma unroll
        for (int j = 0; j < 4; j++)
            #pragma unroll
            for (int r = 0; r < 4; r++) acc[i][j][r] = 0.0f;

    for (int k0 = 0; k0 < K; k0 += 16) {
        // ---- A tile: 128 rows x 16 k -> packed [kp][m], split hi/lo ----
        {
            int grow = rowBase + ar;
            float4 v0 = make_float4(0.f,0.f,0.f,0.f), v1 = v0;
            if (grow < M) {
                const float* ap = &A[(size_t)grow * K + k0 + ahalf * 8];
                v0 = *(const float4*)ap;
                v1 = *(const float4*)(ap + 4);
            }
            float vv[8] = {v0.x, v0.y, v0.z, v0.w, v1.x, v1.y, v1.z, v1.w};
            #pragma unroll
            for (int j = 0; j < 4; j++) {
                unsigned hi, lo;
                bf16_split2(vv[2*j], vv[2*j+1], hi, lo);
                int kp = ahalf * 4 + j;
                Ahip[kp][ar] = hi;
                Alop[kp][ar] = lo;
            }
        }
        // ---- B tile: 16 k x 128 n -> packed [kp][n], split hi/lo ----
        {
            const float* br0 = &B[(size_t)(k0 + 2 * bkp) * N + colBase + bn0];
            float4 t0 = *(const float4*)br0;
            float4 t1 = *(const float4*)(br0 + N);
            uint4 h4, l4;
            bf16_split2(t0.x, t1.x, h4.x, l4.x);
            bf16_split2(t0.y, t1.y, h4.y, l4.y);
            bf16_split2(t0.z, t1.z, h4.z, l4.z);
            bf16_split2(t0.w, t1.w, h4.w, l4.w);
            *(uint4*)&Bhip[bkp][bn0] = h4;
            *(uint4*)&Blop[bkp][bn0] = l4;
        }
        __syncthreads();

        unsigned ah[4][4], al[4][4], bh[4][2], bl[4][2];
        #pragma unroll
        for (int mi = 0; mi < 4; mi++) {
            int m0 = warpRow * 64 + mi * 16;
            ah[mi][0] = Ahip[tg    ][m0 + gr];
            ah[mi][1] = Ahip[tg    ][m0 + gr + 8];
            ah[mi][2] = Ahip[tg + 4][m0 + gr];
            ah[mi][3] = Ahip[tg + 4][m0 + gr + 8];
            al[mi][0] = Alop[tg    ][m0 + gr];
            al[mi][1] = Alop[tg    ][m0 + gr + 8];
            al[mi][2] = Alop[tg + 4][m0 + gr];
            al[mi][3] = Alop[tg + 4][m0 + gr + 8];
        }
        #pragma unroll
        for (int ni = 0; ni < 4; ni++) {
            int n0 = warpCol * 32 + ni * 8;
            bh[ni][0] = Bhip[tg    ][n0 + gr];
            bh[ni][1] = Bhip[tg + 4][n0 + gr];
            bl[ni][0] = Blop[tg    ][n0 + gr];
            bl[ni][1] = Blop[tg + 4][n0 + gr];
        }
        #pragma unroll
        for (int mi = 0; mi < 4; mi++)
            #pragma unroll
            for (int ni = 0; ni < 4; ni++) {
                mma16(acc[mi][ni], ah[mi], bh[ni]);
                mma16(acc[mi][ni], ah[mi], bl[ni]);
                mma16(acc[mi][ni], al[mi], bh[ni]);
            }
        __syncthreads();
    }

    // ---- epilogue ----
    #pragma unroll
    for (int mi = 0; mi < 4; mi++) {
        #pragma unroll
        for (int half = 0; half < 2; half++) {
            int row = rowBase + warpRow * 64 + mi * 16 + gr + half * 8;
            if (row >= M) continue;
            #pragma unroll
            for (int ni = 0; ni < 4; ni++) {
                int col = colBase + warpCol * 32 + ni * 8 + tg * 2;
                float v0 = acc[mi][ni][half * 2 + 0] + (bias ? bias[col]     : 0.0f);
                float v1 = acc[mi][ni][half * 2 + 1] + (bias ? bias[col + 1] : 0.0f);
                if (EPI == 1) {
                    float t0 = 0.7978845608028654f * (v0 + 0.044715f * v0 * v0 * v0);
                    v0 = 0.5f * v0 * (1.0f + tanhf(t0));
                    float t1 = 0.7978845608028654f * (v1 + 0.044715f * v1 * v1 * v1);
                    v1 = 0.5f * v1 * (1.0f + tanhf(t1));
                } else if (EPI == 2) {
                    float g0 = gate[(size_t)row * gate_stride + col];
                    float g1 = gate[(size_t)row * gate_stride + col + 1];
                    v0 = resid[(size_t)row * N + col]     + g0 * v0;
                    v1 = resid[(size_t)row * N + col + 1] + g1 * v1;
                }
                *(float2*)&C[(size_t)row * N + col] = make_float2(v0, v1);
            }
        }
    }
}

// ---------------- launch ----------------------------------------------------
extern "C" void kernel_launch(void* const* d_in, const int* in_sizes, int n_in,
                              void* d_out, int out_size) {
    const float* x      = (const float*)d_in[0];
    const void*  ei     = d_in[1];
    const float* c      = (const float*)d_in[2];
    const float* w_qkv  = (const float*)d_in[3];
    const float* w_proj = (const float*)d_in[4];
    const float* b_proj = (const float*)d_in[5];
    const float* w_mlp1 = (const float*)d_in[6];
    const float* b_mlp1 = (const float*)d_in[7];
    const float* w_mlp2 = (const float*)d_in[8];
    const float* b_mlp2 = (const float*)d_in[9];
    const float* w_ada  = (const float*)d_in[10];
    const float* b_ada  = (const float*)d_in[11];
    float* out = (float*)d_out;

    float *p_sc, *p_mods, *p_xmod, *p_qkv, *p_agg, *p_x1, *p_h1;
    cudaGetSymbolAddress((void**)&p_sc,   g_sc);
    cudaGetSymbolAddress((void**)&p_mods, g_mods);
    cudaGetSymbolAddress((void**)&p_xmod, g_xmod);
    cudaGetSymbolAddress((void**)&p_qkv,  g_qkv);
    cudaGetSymbolAddress((void**)&p_agg,  g_agg);
    cudaGetSymbolAddress((void**)&p_x1,   g_x1);
    cudaGetSymbolAddress((void**)&p_h1,   g_h1);

    const int rowsB = (Nn + 127) / 128;   // 391

    // 0) edge-index dtype probe + conversion
    k_flag_init<<<1, 1>>>();
    k_detect <<<(Ee + 255) / 256, 256>>>(ei);
    k_convert<<<(Ee + 255) / 256, 256>>>(ei);

    // 1) silu(c)
    k_silu<<<(Nn * HIDc + 255) / 256, 256>>>(c, p_sc);
    // 2) mods = silu(c) @ w_ada + b_ada
    bgemm128<0><<<dim3(MODSc / 128, rowsB), 256>>>(p_sc, w_ada, b_ada, p_mods,
                                                   Nn, MODSc, HIDc, nullptr, nullptr, 0);
    // 3) xmod = modulate(ln(x), sh_msa, sc_msa)
    k_ln_mod<<<(Nn + 7) / 8, 256>>>(x, p_mods, 0, HIDc, p_xmod);
    // 4) qkv = xmod @ w_qkv
    bgemm128<0><<<dim3(384 / 128, rowsB), 256>>>(p_xmod, w_qkv, nullptr, p_qkv,
                                                 Nn, 384, HIDc, nullptr, nullptr, 0);
    // 5) init attn scratch
    k_init<<<(Nn * HIDc + 255) / 256, 256>>>();
    // 6) per-edge scores + segment max
    k_edge_score<<<(Ee * 8) / 256, 256>>>(p_qkv);
    // 7) per-edge exp + denominator + message accumulation
    k_edge_msg<<<(Ee * 8) / 256, 256>>>(p_qkv);
    // 8) normalize
    k_norm<<<(Nn * 32 + 255) / 256, 256>>>();
    // 9) x1 = x + g_msa * (agg @ w_proj + b_proj)
    bgemm128<2><<<dim3(1, rowsB), 256>>>(p_agg, w_proj, b_proj, p_x1,
                                         Nn, HIDc, HIDc, x, p_mods + 2 * HIDc, MODSc);
    // 10) xmod = modulate(ln(x1), sh_mlp, sc_mlp)
    k_ln_mod<<<(Nn + 7) / 8, 256>>>(p_x1, p_mods, 3 * HIDc, 4 * HIDc, p_xmod);
    // 11) h1 = gelu(xmod @ w_mlp1 + b_mlp1)
    bgemm128<1><<<dim3(MLPc / 128, rowsB), 256>>>(p_xmod, w_mlp1, b_mlp1, p_h1,
                                                  Nn, MLPc, HIDc, nullptr, nullptr, 0);
    // 12) out = x1 + g_mlp * (h1 @ w_mlp2 + b_mlp2)
    bgemm128<2><<<dim3(1, rowsB), 256>>>(p_h1, w_mlp2, b_mlp2, out,
                                         Nn, HIDc, MLPc, p_x1, p_mods + 5 * HIDc, MODSc);
}

// round 7
// speedup vs baseline: 1.5492x; 1.0673x over previous
#include <cuda_runtime.h>
#include <cuda_bf16.h>
#include <math.h>

#define Nn   50000
#define Ee   800000
#define HIDc 128
#define MLPc 512
#define MODSc 768

// packed weight split buffer offsets (in uints; kp-major, [K/2][N])
#define W_ADA_OFF   0            // 64*768 = 49152
#define W_QKV_OFF   49152        // 64*384 = 24576
#define W_PROJ_OFF  73728        // 64*128 = 8192
#define W_MLP1_OFF  81920        // 64*512 = 32768
#define W_MLP2_OFF  114688       // 256*128 = 32768
#define W_TOTAL     147456

// ---------------- scratch (device globals; no allocation allowed) ----------
__device__ float g_mods[Nn * MODSc];
__device__ float g_xmod[Nn * HIDc];
__device__ float g_qkv [Nn * 3 * HIDc];
__device__ float g_score[(size_t)Ee * 8];
__device__ float g_smax[Nn * 8];
__device__ float g_den [Nn * 8];
__device__ float g_agg [Nn * HIDc];
__device__ float g_x1  [Nn * HIDc];
__device__ float g_h1  [Nn * MLPc];
__device__ int   g_src [Ee];
__device__ int   g_dst [Ee];
__device__ int   g_is64;
__device__ unsigned g_whi[W_TOTAL];
__device__ unsigned g_wlo[W_TOTAL];

// ---------------- helpers ---------------------------------------------------
__device__ __forceinline__ void atomicMaxFloat(float* addr, float value) {
    if (value >= 0.0f)
        atomicMax((int*)addr, __float_as_int(value));
    else
        atomicMin((unsigned int*)addr, __float_as_uint(value));
}

__device__ __forceinline__ void redAdd4(float* addr, float4 v) {
    asm volatile("red.global.add.v4.f32 [%0], {%1, %2, %3, %4};"
                 :: "l"(addr), "f"(v.x), "f"(v.y), "f"(v.z), "f"(v.w)
                 : "memory");
}

// split a float pair into packed bf16x2 hi and lo
__device__ __forceinline__ void bf16_split2(float e, float o, unsigned& hi, unsigned& lo) {
    __nv_bfloat162 h2 = __floats2bfloat162_rn(e, o);
    float he = __bfloat162float(h2.x);
    float ho = __bfloat162float(h2.y);
    __nv_bfloat162 l2 = __floats2bfloat162_rn(e - he, o - ho);
    hi = *(unsigned*)&h2;
    lo = *(unsigned*)&l2;
}

__device__ __forceinline__ void mma16(float* c, const unsigned* a, const unsigned* b) {
    asm volatile("mma.sync.aligned.m16n8k16.row.col.f32.bf16.bf16.f32 "
                 "{%0,%1,%2,%3}, {%4,%5,%6,%7}, {%8,%9}, {%0,%1,%2,%3};"
                 : "+f"(c[0]), "+f"(c[1]), "+f"(c[2]), "+f"(c[3])
                 : "r"(a[0]), "r"(a[1]), "r"(a[2]), "r"(a[3]),
                   "r"(b[0]), "r"(b[1]));
}

// ---------------- weight pre-split ------------------------------------------
__global__ void k_wsplit(const float* __restrict__ W, int Kd, int N,
                         unsigned* __restrict__ hi, unsigned* __restrict__ lo) {
    int t = blockIdx.x * blockDim.x + threadIdx.x;
    int total = (Kd / 2) * N;
    if (t >= total) return;
    int kp = t / N, n = t - kp * N;
    float e = W[(size_t)(2 * kp) * N + n];
    float o = W[(size_t)(2 * kp + 1) * N + n];
    unsigned h, l;
    bf16_split2(e, o, h, l);
    hi[t] = h; lo[t] = l;
}

// ---------------- edge-index dtype probe + conversion ------------------------
__global__ void k_flag_init() { g_is64 = 1; }

__global__ void k_detect(const void* __restrict__ ei) {
    int t = blockIdx.x * blockDim.x + threadIdx.x;
    if (t >= Ee) return;
    long long v = ((const long long*)ei)[t];
    if (v < 0 || v >= (long long)Nn) g_is64 = 0;
}

__global__ void k_convert(const void* __restrict__ ei) {
    int t = blockIdx.x * blockDim.x + threadIdx.x;
    if (t >= Ee) return;
    if (g_is64) {
        g_src[t] = (int)((const long long*)ei)[t];
        g_dst[t] = (int)((const long long*)ei)[Ee + t];
    } else {
        g_src[t] = ((const int*)ei)[t];
        g_dst[t] = ((const int*)ei)[Ee + t];
    }
}

// ---------------- elementwise kernels ---------------------------------------
__global__ void k_init() {
    int t = blockIdx.x * blockDim.x + threadIdx.x;
    if (t < Nn * HIDc) g_agg[t] = 0.0f;
    if (t < Nn * 8) { g_den[t] = 0.0f; g_smax[t] = -INFINITY; }
}

__global__ void k_ln_mod(const float* __restrict__ x, const float* __restrict__ mods,
                         int shift_off, int scale_off, float* __restrict__ out) {
    int warp = (blockIdx.x * blockDim.x + threadIdx.x) >> 5;
    int lane = threadIdx.x & 31;
    if (warp >= Nn) return;
    const float4 xv = *(const float4*)&x[(size_t)warp * HIDc + lane * 4];
    float s  = xv.x + xv.y + xv.z + xv.w;
    float s2 = xv.x*xv.x + xv.y*xv.y + xv.z*xv.z + xv.w*xv.w;
    #pragma unroll
    for (int o = 16; o; o >>= 1) {
        s  += __shfl_xor_sync(0xffffffffu, s,  o);
        s2 += __shfl_xor_sync(0xffffffffu, s2, o);
    }
    float mean = s * (1.0f / 128.0f);
    float var  = s2 * (1.0f / 128.0f) - mean * mean;
    float rstd = rsqrtf(var + 1e-6f);
    const float4 sh = *(const float4*)&mods[(size_t)warp * MODSc + shift_off + lane * 4];
    const float4 sc = *(const float4*)&mods[(size_t)warp * MODSc + scale_off + lane * 4];
    float4 o4;
    o4.x = (xv.x - mean) * rstd * (1.0f + sc.x) + sh.x;
    o4.y = (xv.y - mean) * rstd * (1.0f + sc.y) + sh.y;
    o4.z = (xv.z - mean) * rstd * (1.0f + sc.z) + sh.z;
    o4.w = (xv.w - mean) * rstd * (1.0f + sc.w) + sh.w;
    *(float4*)&out[(size_t)warp * HIDc + lane * 4] = o4;
}

// ---------------- edge kernels ----------------------------------------------
__global__ void k_edge_score(const float* __restrict__ qkv) {
    long long t = (long long)blockIdx.x * blockDim.x + threadIdx.x;
    if (t >= (long long)Ee * 8) return;
    int e = (int)(t >> 3);
    int h = (int)(t & 7);
    int src = g_src[e];
    int dst = g_dst[e];
    const float* q = &qkv[(size_t)dst * 384 + h * 16];
    const float* k = &qkv[(size_t)src * 384 + 128 + h * 16];
    float d = 0.0f;
    #pragma unroll
    for (int i = 0; i < 4; i++) {
        float4 qv = *(const float4*)&q[i * 4];
        float4 kv = *(const float4*)&k[i * 4];
        d += qv.x*kv.x + qv.y*kv.y + qv.z*kv.z + qv.w*kv.w;
    }
    d *= 0.25f;
    g_score[t] = d;
    atomicMaxFloat(&g_smax[dst * 8 + h], d);
}

__global__ void k_edge_msg(const float* __restrict__ qkv) {
    long long t = (long long)blockIdx.x * blockDim.x + threadIdx.x;
    if (t >= (long long)Ee * 8) return;
    int e = (int)(t >> 3);
    int h = (int)(t & 7);
    int src = g_src[e];
    int dst = g_dst[e];
    float sc = g_score[t];
    float ex = expf(sc - g_smax[dst * 8 + h]);
    atomicAdd(&g_den[dst * 8 + h], ex);
    const float* v = &qkv[(size_t)src * 384 + 256 + h * 16];
    float* a = &g_agg[(size_t)dst * HIDc + h * 16];
    #pragma unroll
    for (int i = 0; i < 4; i++) {
        float4 vv = *(const float4*)&v[i * 4];
        redAdd4(&a[i * 4], make_float4(vv.x * ex, vv.y * ex, vv.z * ex, vv.w * ex));
    }
}

__global__ void k_norm() {
    int t = blockIdx.x * blockDim.x + threadIdx.x;
    if (t >= Nn * 32) return;
    int n = t >> 5;
    int h = (t >> 2) & 7;
    float dd = g_den[n * 8 + h];
    float inv = (dd > 0.0f) ? (1.0f / dd) : 0.0f;
    float4 v = *(float4*)&g_agg[t * 4];
    v.x *= inv; v.y *= inv; v.z *= inv; v.w *= inv;
    *(float4*)&g_agg[t * 4] = v;
}

// ---------------- 3xBF16 tensor-core GEMM (pre-split B) ---------------------
// C[M,N] = epi(A[M,K] @ B[K,N] + bias), B given as packed bf16x2 hi/lo [K/2][N]
// 128x128 block tile, BK=16, 256 threads, 8 warps (2x4), mma.m16n8k16.bf16.
// PRE 0: raw A   PRE 1: silu(A)
// EPI 0: +bias   EPI 1: gelu(tanh)   EPI 2: resid + gate*(acc+bias)
#define PADg 136

template<int EPI, int PRE>
__global__ __launch_bounds__(256)
void bgemm128(const float* __restrict__ A,
              const unsigned* __restrict__ Bhi, const unsigned* __restrict__ Blo,
              const float* __restrict__ bias, float* __restrict__ C,
              int M, int N, int K,
              const float* __restrict__ resid,
              const float* __restrict__ gate, int gate_stride) {
    __shared__ unsigned Ahip[8][PADg], Alop[8][PADg];
    __shared__ unsigned Bhip[8][PADg], Blop[8][PADg];

    const int tid = threadIdx.x;
    const int warpId = tid >> 5;
    const int lane = tid & 31;
    const int gr = lane >> 2;
    const int tg = lane & 3;
    const int warpRow = warpId >> 2;
    const int warpCol = warpId & 3;
    const int rowBase = blockIdx.y * 128;
    const int colBase = blockIdx.x * 128;

    const int ar = tid & 127;
    const int ahalf = tid >> 7;
    const int bkp = tid >> 5;
    const int bn0 = lane * 4;
    const int arow_ok = (rowBase + ar) < M;
    const float* aBase = &A[(size_t)(rowBase + ar) * K + ahalf * 8];
    const unsigned* bhBase = &Bhi[(size_t)bkp * N + colBase + bn0];
    const unsigned* blBase = &Blo[(size_t)bkp * N + colBase + bn0];

    float acc[4][4][4];
    #pragma unroll
    for (int i = 0; i < 4; i++)
        #pragma unroll
        for (int j = 0; j < 4; j++)
            #pragma unroll
            for (int r = 0; r < 4; r++) acc[i][j][r] = 0.0f;

    float4 aR0 = make_float4(0.f,0.f,0.f,0.f), aR1 = aR0;
    uint4 bhR, blR;

    // prefetch iter 0
    if (arow_ok) { aR0 = *(const float4*)aBase; aR1 = *(const float4*)(aBase + 4); }
    bhR = *(const uint4*)bhBase;
    blR = *(const uint4*)blBase;

    for (int k0 = 0; k0 < K; k0 += 16) {
        // ---- store staged regs to smem ----
        {
            float vv[8] = {aR0.x, aR0.y, aR0.z, aR0.w, aR1.x, aR1.y, aR1.z, aR1.w};
            if (PRE == 1) {
                #pragma unroll
                for (int j = 0; j < 8; j++) vv[j] = vv[j] / (1.0f + expf(-vv[j]));
            }
            #pragma unroll
            for (int j = 0; j < 4; j++) {
                unsigned hi, lo;
                bf16_split2(vv[2*j], vv[2*j+1], hi, lo);
                Ahip[ahalf * 4 + j][ar] = hi;
                Alop[ahalf * 4 + j][ar] = lo;
            }
            *(uint4*)&Bhip[bkp][bn0] = bhR;
            *(uint4*)&Blop[bkp][bn0] = blR;
        }
        __syncthreads();

        // ---- prefetch next iter while MMAs run ----
        if (k0 + 16 < K) {
            if (arow_ok) {
                aR0 = *(const float4*)(aBase + k0 + 16);
                aR1 = *(const float4*)(aBase + k0 + 20);
            }
            bhR = *(const uint4*)(bhBase + (size_t)(k0 / 2 + 8) * N);
            blR = *(const uint4*)(blBase + (size_t)(k0 / 2 + 8) * N);
        }

        unsigned ah[4][4], al[4][4], bh[4][2], bl[4][2];
        #pragma unroll
        for (int mi = 0; mi < 4; mi++) {
            int m0 = warpRow * 64 + mi * 16;
            ah[mi][0] = Ahip[tg    ][m0 + gr];
            ah[mi][1] = Ahip[tg    ][m0 + gr + 8];
            ah[mi][2] = Ahip[tg + 4][m0 + gr];
            ah[mi][3] = Ahip[tg + 4][m0 + gr + 8];
            al[mi][0] = Alop[tg    ][m0 + gr];
            al[mi][1] = Alop[tg    ][m0 + gr + 8];
            al[mi][2] = Alop[tg + 4][m0 + gr];
            al[mi][3] = Alop[tg + 4][m0 + gr + 8];
        }
        #pragma unroll
        for (int ni = 0; ni < 4; ni++) {
            int n0 = warpCol * 32 + ni * 8;
            bh[ni][0] = Bhip[tg    ][n0 + gr];
            bh[ni][1] = Bhip[tg + 4][n0 + gr];
            bl[ni][0] = Blop[tg    ][n0 + gr];
            bl[ni][1] = Blop[tg + 4][n0 + gr];
        }
        // three independent passes -> no back-to-back RAW on accumulators
        #pragma unroll
        for (int mi = 0; mi < 4; mi++)
            #pragma unroll
            for (int ni = 0; ni < 4; ni++)
                mma16(acc[mi][ni], ah[mi], bh[ni]);
        #pragma unroll
        for (int mi = 0; mi < 4; mi++)
            #pragma unroll
            for (int ni = 0; ni < 4; ni++)
                mma16(acc[mi][ni], ah[mi], bl[ni]);
        #pragma unroll
        for (int mi = 0; mi < 4; mi++)
            #pragma unroll
            for (int ni = 0; ni < 4; ni++)
                mma16(acc[mi][ni], al[mi], bh[ni]);
        __syncthreads();
    }

    // ---- epilogue ----
    #pragma unroll
    for (int mi = 0; mi < 4; mi++) {
        #pragma unroll
        for (int half = 0; half < 2; half++) {
            int row = rowBase + warpRow * 64 + mi * 16 + gr + half * 8;
            if (row >= M) continue;
            #pragma unroll
            for (int ni = 0; ni < 4; ni++) {
                int col = colBase + warpCol * 32 + ni * 8 + tg * 2;
                float v0 = acc[mi][ni][half * 2 + 0] + (bias ? bias[col]     : 0.0f);
                float v1 = acc[mi][ni][half * 2 + 1] + (bias ? bias[col + 1] : 0.0f);
                if (EPI == 1) {
                    float t0 = 0.7978845608028654f * (v0 + 0.044715f * v0 * v0 * v0);
                    v0 = 0.5f * v0 * (1.0f + tanhf(t0));
                    float t1 = 0.7978845608028654f * (v1 + 0.044715f * v1 * v1 * v1);
                    v1 = 0.5f * v1 * (1.0f + tanhf(t1));
                } else if (EPI == 2) {
                    float g0 = gate[(size_t)row * gate_stride + col];
                    float g1 = gate[(size_t)row * gate_stride + col + 1];
                    v0 = resid[(size_t)row * N + col]     + g0 * v0;
                    v1 = resid[(size_t)row * N + col + 1] + g1 * v1;
                }
                *(float2*)&C[(size_t)row * N + col] = make_float2(v0, v1);
            }
        }
    }
}

// ---------------- launch ----------------------------------------------------
extern "C" void kernel_launch(void* const* d_in, const int* in_sizes, int n_in,
                              void* d_out, int out_size) {
    const float* x      = (const float*)d_in[0];
    const void*  ei     = d_in[1];
    const float* c      = (const float*)d_in[2];
    const float* w_qkv  = (const float*)d_in[3];
    const float* w_proj = (const float*)d_in[4];
    const float* b_proj = (const float*)d_in[5];
    const float* w_mlp1 = (const float*)d_in[6];
    const float* b_mlp1 = (const float*)d_in[7];
    const float* w_mlp2 = (const float*)d_in[8];
    const float* b_mlp2 = (const float*)d_in[9];
    const float* w_ada  = (const float*)d_in[10];
    const float* b_ada  = (const float*)d_in[11];
    float* out = (float*)d_out;

    float *p_mods, *p_xmod, *p_qkv, *p_agg, *p_x1, *p_h1;
    unsigned *p_whi, *p_wlo;
    cudaGetSymbolAddress((void**)&p_mods, g_mods);
    cudaGetSymbolAddress((void**)&p_xmod, g_xmod);
    cudaGetSymbolAddress((void**)&p_qkv,  g_qkv);
    cudaGetSymbolAddress((void**)&p_agg,  g_agg);
    cudaGetSymbolAddress((void**)&p_x1,   g_x1);
    cudaGetSymbolAddress((void**)&p_h1,   g_h1);
    cudaGetSymbolAddress((void**)&p_whi,  g_whi);
    cudaGetSymbolAddress((void**)&p_wlo,  g_wlo);

    const int rowsB = (Nn + 127) / 128;   // 391

    // 0) edge-index dtype probe + conversion; weight pre-split
    k_flag_init<<<1, 1>>>();
    k_detect <<<(Ee + 255) / 256, 256>>>(ei);
    k_convert<<<(Ee + 255) / 256, 256>>>(ei);
    k_wsplit<<<(64 * MODSc + 255) / 256, 256>>>(w_ada,  HIDc, MODSc, p_whi + W_ADA_OFF,  p_wlo + W_ADA_OFF);
    k_wsplit<<<(64 * 384   + 255) / 256, 256>>>(w_qkv,  HIDc, 384,   p_whi + W_QKV_OFF,  p_wlo + W_QKV_OFF);
    k_wsplit<<<(64 * HIDc  + 255) / 256, 256>>>(w_proj, HIDc, HIDc,  p_whi + W_PROJ_OFF, p_wlo + W_PROJ_OFF);
    k_wsplit<<<(64 * MLPc  + 255) / 256, 256>>>(w_mlp1, HIDc, MLPc,  p_whi + W_MLP1_OFF, p_wlo + W_MLP1_OFF);
    k_wsplit<<<(256 * HIDc + 255) / 256, 256>>>(w_mlp2, MLPc, HIDc,  p_whi + W_MLP2_OFF, p_wlo + W_MLP2_OFF);

    // 1) mods = silu(c) @ w_ada + b_ada   (silu fused into A-load)
    bgemm128<0,1><<<dim3(MODSc / 128, rowsB), 256>>>(c, p_whi + W_ADA_OFF, p_wlo + W_ADA_OFF,
                                                     b_ada, p_mods, Nn, MODSc, HIDc, nullptr, nullptr, 0);
    // 2) xmod = modulate(ln(x), sh_msa, sc_msa)
    k_ln_mod<<<(Nn + 7) / 8, 256>>>(x, p_mods, 0, HIDc, p_xmod);
    // 3) qkv = xmod @ w_qkv
    bgemm128<0,0><<<dim3(384 / 128, rowsB), 256>>>(p_xmod, p_whi + W_QKV_OFF, p_wlo + W_QKV_OFF,
                                                   nullptr, p_qkv, Nn, 384, HIDc, nullptr, nullptr, 0);
    // 4) init attn scratch
    k_init<<<(Nn * HIDc + 255) / 256, 256>>>();
    // 5) per-edge scores + segment max
    k_edge_score<<<(Ee * 8) / 256, 256>>>(p_qkv);
    // 6) per-edge exp + denominator + message accumulation
    k_edge_msg<<<(Ee * 8) / 256, 256>>>(p_qkv);
    // 7) normalize
    k_norm<<<(Nn * 32 + 255) / 256, 256>>>();
    // 8) x1 = x + g_msa * (agg @ w_proj + b_proj)
    bgemm128<2,0><<<dim3(1, rowsB), 256>>>(p_agg, p_whi + W_PROJ_OFF, p_wlo + W_PROJ_OFF,
                                           b_proj, p_x1, Nn, HIDc, HIDc, x, p_mods + 2 * HIDc, MODSc);
    // 9) xmod = modulate(ln(x1), sh_mlp, sc_mlp)
    k_ln_mod<<<(Nn + 7) / 8, 256>>>(p_x1, p_mods, 3 * HIDc, 4 * HIDc, p_xmod);
    // 10) h1 = gelu(xmod @ w_mlp1 + b_mlp1)
    bgemm128<1,0><<<dim3(MLPc / 128, rowsB), 256>>>(p_xmod, p_whi + W_MLP1_OFF, p_wlo + W_MLP1_OFF,
                                                    b_mlp1, p_h1, Nn, MLPc, HIDc, nullptr, nullptr, 0);
    // 11) out = x1 + g_mlp * (h1 @ w_mlp2 + b_mlp2)
    bgemm128<2,0><<<dim3(1, rowsB), 256>>>(p_h1, p_whi + W_MLP2_OFF, p_wlo + W_MLP2_OFF,
                                           b_mlp2, out, Nn, HIDc, MLPc, p_x1, p_mods + 5 * HIDc, MODSc);
}